// round 16
// baseline (speedup 1.0000x reference)
#include <cuda_runtime.h>
#include <cuda_bf16.h>
#include <math.h>
#include <stdint.h>

#define B_ 8
#define T_ 2048
#define C_ 1024
#define H_ 64

// Scratch (device globals: allocation-free)
__device__ float g_q[B_ * T_ * H_];     // 8*q (logit scale folded into Wq)
__device__ float g_k[B_ * T_ * H_];
__device__ float g_v[B_ * T_ * H_];

// ===========================================================================
// Warp-level tensor core helpers (sm_80+ features: compile for plain sm_103)
// ===========================================================================
__device__ __forceinline__ uint32_t smem_u32(const void* p) {
    uint32_t a;
    asm("{ .reg .u64 t; cvta.to.shared.u64 t, %1; cvt.u32.u64 %0, t; }"
        : "=r"(a) : "l"(p));
    return a;
}

#define LDSM4(r0, r1, r2, r3, addr) \
    asm volatile("ldmatrix.sync.aligned.m8n8.x4.shared.b16 {%0,%1,%2,%3}, [%4];" \
                 : "=r"(r0), "=r"(r1), "=r"(r2), "=r"(r3) : "r"(addr))
#define LDSM2(r0, r1, addr) \
    asm volatile("ldmatrix.sync.aligned.m8n8.x2.shared.b16 {%0,%1}, [%2];" \
                 : "=r"(r0), "=r"(r1) : "r"(addr))
#define LDSM2T(r0, r1, addr) \
    asm volatile("ldmatrix.sync.aligned.m8n8.x2.trans.shared.b16 {%0,%1}, [%2];" \
                 : "=r"(r0), "=r"(r1) : "r"(addr))

__device__ __forceinline__ void mma16816(float* c,
                                         uint32_t a0, uint32_t a1,
                                         uint32_t a2, uint32_t a3,
                                         uint32_t b0, uint32_t b1) {
    asm volatile(
        "mma.sync.aligned.m16n8k16.row.col.f32.bf16.bf16.f32 "
        "{%0,%1,%2,%3}, {%4,%5,%6,%7}, {%8,%9}, {%0,%1,%2,%3};"
        : "+f"(c[0]), "+f"(c[1]), "+f"(c[2]), "+f"(c[3])
        : "r"(a0), "r"(a1), "r"(a2), "r"(a3), "r"(b0), "r"(b1));
}

// split one float4 into hi/lo bf16x4 (packed as uint2 each)
__device__ __forceinline__ void bf16_split4(float4 v, uint2& hv, uint2& lv) {
    __nv_bfloat16 h0 = __float2bfloat16_rn(v.x);
    __nv_bfloat16 h1 = __float2bfloat16_rn(v.y);
    __nv_bfloat16 h2 = __float2bfloat16_rn(v.z);
    __nv_bfloat16 h3 = __float2bfloat16_rn(v.w);
    __nv_bfloat16 l0 = __float2bfloat16_rn(v.x - __bfloat162float(h0));
    __nv_bfloat16 l1 = __float2bfloat16_rn(v.y - __bfloat162float(h1));
    __nv_bfloat16 l2 = __float2bfloat16_rn(v.z - __bfloat162float(h2));
    __nv_bfloat16 l3 = __float2bfloat16_rn(v.w - __bfloat162float(h3));
    hv.x = (uint32_t)__bfloat16_as_ushort(h0) |
           ((uint32_t)__bfloat16_as_ushort(h1) << 16);
    hv.y = (uint32_t)__bfloat16_as_ushort(h2) |
           ((uint32_t)__bfloat16_as_ushort(h3) << 16);
    lv.x = (uint32_t)__bfloat16_as_ushort(l0) |
           ((uint32_t)__bfloat16_as_ushort(l1) << 16);
    lv.y = (uint32_t)__bfloat16_as_ushort(l2) |
           ((uint32_t)__bfloat16_as_ushort(l3) << 16);
}

// split two fp32 values into packed hi/lo bf16x2
__device__ __forceinline__ void packsplit2(float a, float b,
                                           uint32_t& h, uint32_t& l) {
    __nv_bfloat16 ha = __float2bfloat16_rn(a);
    __nv_bfloat16 hb = __float2bfloat16_rn(b);
    __nv_bfloat16 la = __float2bfloat16_rn(a - __bfloat162float(ha));
    __nv_bfloat16 lb = __float2bfloat16_rn(b - __bfloat162float(hb));
    h = (uint32_t)__bfloat16_as_ushort(ha) |
        ((uint32_t)__bfloat16_as_ushort(hb) << 16);
    l = (uint32_t)__bfloat16_as_ushort(la) |
        ((uint32_t)__bfloat16_as_ushort(lb) << 16);
}

// ---------------------------------------------------------------------------
// Tensor-core projection GEMM (mma.sync bf16 hi/lo split, 3 MMAs per pair):
//   out[m][h] = sum_c x[m][c] * W[h][c],  M=16384, N=192, K=1024.
// Block: 128 M x 192 N, 512 threads = 16 warps (8 x 2), warp tile 16 x 96.
// BK=32, double-buffered smem, 40-bf16 (80 B) row stride.
// ---------------------------------------------------------------------------
#define PSTRB 40
#define BUF_ELE (320 * PSTRB * 2)
#define AH_OFF 0
#define AL_OFF (128 * PSTRB)
#define BH_OFF (256 * PSTRB)
#define BL_OFF (448 * PSTRB)
#define PROJ_SMEM (2 * BUF_ELE * 2)

__global__ __launch_bounds__(512, 1)
void proj_kernel(const float* __restrict__ x,
                 const float* __restrict__ Wk,
                 const float* __restrict__ Wq,
                 const float* __restrict__ Wv)
{
    extern __shared__ __align__(16) char smem[];
    __nv_bfloat16* sb16 = (__nv_bfloat16*)smem;
    const uint32_t sb = smem_u32(smem);

    const int tid = threadIdx.x;
    const int wid = tid >> 5;
    const int lane = tid & 31;
    const int row0 = blockIdx.x * 128;
    const int warp_m = (wid >> 1) * 16;   // 8 m-groups
    const int warp_n = (wid & 1) * 96;    // 2 n-halves

    // A: 1024 float4 -> 2/thread
    int ar[2], ac[2];
#pragma unroll
    for (int i = 0; i < 2; i++) {
        int idx = tid + i * 512;
        ar[i] = idx >> 3;
        ac[i] = (idx & 7) << 2;
    }
    // B: 1536 float4 -> 3/thread
    const float* wp[3];
    float wsc[3];
    int wr[3], wc[3];
#pragma unroll
    for (int i = 0; i < 3; i++) {
        int idx = tid + i * 512;
        int r = idx >> 3;
        wr[i] = r;
        wc[i] = (idx & 7) << 2;
        if (r < 64)       { wp[i] = Wk + (size_t)r * C_;         wsc[i] = 1.f; }
        else if (r < 128) { wp[i] = Wq + (size_t)(r - 64) * C_;  wsc[i] = 8.f; }
        else              { wp[i] = Wv + (size_t)(r - 128) * C_; wsc[i] = 1.f; }
    }

    const uint32_t a_lrow = (uint32_t)(lane & 15);
    const uint32_t a_koff = (uint32_t)((lane >> 4) * 16);
    const uint32_t b_lrow = (uint32_t)(lane & 7);
    const uint32_t b_koff = (uint32_t)(((lane >> 3) & 1) * 16);

    float acc[12][4];
#pragma unroll
    for (int nj = 0; nj < 12; nj++)
#pragma unroll
        for (int q = 0; q < 4; q++) acc[nj][q] = 0.f;

    {
        __nv_bfloat16* base = sb16;
#pragma unroll
        for (int i = 0; i < 2; i++) {
            float4 v = *(const float4*)(x + (size_t)(row0 + ar[i]) * C_ + ac[i]);
            uint2 hv, lv; bf16_split4(v, hv, lv);
            int off = ar[i] * PSTRB + ac[i];
            *(uint2*)(base + AH_OFF + off) = hv;
            *(uint2*)(base + AL_OFF + off) = lv;
        }
#pragma unroll
        for (int i = 0; i < 3; i++) {
            float4 v = *(const float4*)(wp[i] + wc[i]);
            v.x *= wsc[i]; v.y *= wsc[i]; v.z *= wsc[i]; v.w *= wsc[i];
            uint2 hv, lv; bf16_split4(v, hv, lv);
            int off = wr[i] * PSTRB + wc[i];
            *(uint2*)(base + BH_OFF + off) = hv;
            *(uint2*)(base + BL_OFF + off) = lv;
        }
    }
    __syncthreads();

    const int NKT = C_ / 32;
    for (int kt = 0; kt < NKT; kt++) {
        const int cur = kt & 1;
        const bool more = (kt + 1 < NKT);

        float4 rxa[2], rxb[3];
        if (more) {
            const int kc = (kt + 1) * 32;
#pragma unroll
            for (int i = 0; i < 2; i++)
                rxa[i] = *(const float4*)(x + (size_t)(row0 + ar[i]) * C_ + kc + ac[i]);
#pragma unroll
            for (int i = 0; i < 3; i++) {
                float4 v = *(const float4*)(wp[i] + kc + wc[i]);
                v.x *= wsc[i]; v.y *= wsc[i]; v.z *= wsc[i]; v.w *= wsc[i];
                rxb[i] = v;
            }
        }

        const uint32_t bufb = sb + cur * BUF_ELE * 2;
#pragma unroll
        for (int ks = 0; ks < 2; ks++) {
            const uint32_t kb = ks * 32;
            uint32_t ah[4], al[4];
            uint32_t rowa = warp_m + a_lrow;
            uint32_t aaddr = bufb + rowa * (PSTRB * 2) + a_koff + kb;
            LDSM4(ah[0], ah[1], ah[2], ah[3], aaddr);
            LDSM4(al[0], al[1], al[2], al[3], aaddr + AL_OFF * 2);
#pragma unroll
            for (int nj = 0; nj < 12; nj++) {
                uint32_t rowb = warp_n + nj * 8 + b_lrow;
                uint32_t baddr = bufb + BH_OFF * 2 + rowb * (PSTRB * 2) +
                                 b_koff + kb;
                uint32_t bh0, bh1, bl0, bl1;
                LDSM2(bh0, bh1, baddr);
                LDSM2(bl0, bl1, baddr + (BL_OFF - BH_OFF) * 2);
                mma16816(acc[nj], ah[0], ah[1], ah[2], ah[3], bh0, bh1);
                mma16816(acc[nj], ah[0], ah[1], ah[2], ah[3], bl0, bl1);
                mma16816(acc[nj], al[0], al[1], al[2], al[3], bh0, bh1);
            }
        }

        if (more) {
            __nv_bfloat16* base = sb16 + (cur ^ 1) * BUF_ELE;
#pragma unroll
            for (int i = 0; i < 2; i++) {
                uint2 hv, lv; bf16_split4(rxa[i], hv, lv);
                int off = ar[i] * PSTRB + ac[i];
                *(uint2*)(base + AH_OFF + off) = hv;
                *(uint2*)(base + AL_OFF + off) = lv;
            }
#pragma unroll
            for (int i = 0; i < 3; i++) {
                uint2 hv, lv; bf16_split4(rxb[i], hv, lv);
                int off = wr[i] * PSTRB + wc[i];
                *(uint2*)(base + BH_OFF + off) = hv;
                *(uint2*)(base + BL_OFF + off) = lv;
            }
        }
        __syncthreads();
    }

    const int erow = lane >> 2;
    const int ecol = (lane & 3) * 2;
    {
        const int rg = row0 + warp_m + erow;
#pragma unroll
        for (int nj = 0; nj < 12; nj++) {
            const int n = warp_n + nj * 8 + ecol;
            const int s = n >> 6;
            const int h = n & 63;
            float* op = (s == 0) ? g_k : (s == 1) ? g_q : g_v;
            *(float2*)&op[(size_t)rg * H_ + h] =
                make_float2(acc[nj][0], acc[nj][1]);
            *(float2*)&op[(size_t)(rg + 8) * H_ + h] =
                make_float2(acc[nj][2], acc[nj][3]);
        }
    }
}

// ---------------------------------------------------------------------------
// Tensor-core flash attention (mma.sync, bf16 hi/lo split, causal).
// BM=64 q rows, BN=64 keys/tile. 384 threads:
//   warps 0-7 = consumers: warp pair (w, w+4) shares a 16-row group;
//     w<4 handles keys/d 0..31, w>=4 handles keys/d 32..63.
//     Partial softmax stats exchanged via smem; P staged in smem (bf16 hi/lo).
//   warps 8-11 = producers (LDG fp32 -> split bf16 -> STS, double-buffered KV)
// Paired q-tiles (j, 31-j): 33 equal tiles per block, 128 blocks (16x8).
// Row stride 72 bf16 (144 B): conflict-free ldmatrix.
// ---------------------------------------------------------------------------
#define AQH 0
#define AQL 9216
#define APH 18432
#define APL 27648
#define ASTAT 36864           // float[2][2][64] = 1024 bytes
#define ABUF 37888            // two KV buffers
#define AKH 0
#define AKL 9216
#define AVH 18432
#define AVL 27648
#define ABUFSZ 36864
#define ASTR 72               // row stride in bf16
#define AROWB 144             // row stride in bytes
#define ATTN_SMEM (ABUF + 2 * ABUFSZ)   // 111616 bytes

__global__ __launch_bounds__(384, 1)
void attn_kernel(float* __restrict__ out)
{
    extern __shared__ __align__(16) char smem[];
    __nv_bfloat16* s16 = (__nv_bfloat16*)smem;
    float* st = (float*)(smem + ASTAT);
    const uint32_t sb = smem_u32(smem);

    const int tid = threadIdx.x;
    const int wid = tid >> 5;
    const int lane = tid & 31;
    const int b = blockIdx.y;
    const bool cons = (wid < 8);

    const float* qg = g_q + (size_t)b * T_ * H_;
    const float* kg = g_k + (size_t)b * T_ * H_;
    const float* vg = g_v + (size_t)b * T_ * H_;

    // producer load slots (threads 256..383)
    const int pt = tid - 256;
    int prow[8], pcol[8];
#pragma unroll
    for (int i = 0; i < 8; i++) {
        int idx = pt + i * 128;
        prow[i] = idx >> 4;
        pcol[i] = (idx & 15) << 2;
    }

    // consumer constants
    const int rg_ = wid & 3;
    const int half = (wid >> 2) & 1;
    const int warp_m = rg_ * 16;
    const int n_base = half * 32;      // also d-half base
    const uint32_t a_lrow = (uint32_t)(lane & 15);
    const uint32_t a_koff = (uint32_t)((lane >> 4) * 16);
    const uint32_t b_lrow = (uint32_t)(lane & 7);
    const uint32_t b_koff = (uint32_t)(((lane >> 3) & 1) * 16);
    const int qrow = lane >> 2;
    const int qcol = (lane & 3) * 2;

#pragma unroll 1
    for (int pass = 0; pass < 2; pass++) {
        const int qb = pass ? (31 - (int)blockIdx.x) : (int)blockIdx.x;
        const int q0 = qb * 64;
        const int ntiles = qb + 1;

        __syncthreads();   // previous pass fully consumed

        if (!cons) {
            // Q tile (holds 8*q already)
#pragma unroll
            for (int i = 0; i < 8; i++) {
                float4 v = *(const float4*)(qg + (size_t)(q0 + prow[i]) * H_ + pcol[i]);
                uint2 hv, lv; bf16_split4(v, hv, lv);
                int off = prow[i] * ASTR + pcol[i];
                *(uint2*)(s16 + (AQH >> 1) + off) = hv;
                *(uint2*)(s16 + (AQL >> 1) + off) = lv;
            }
            // KV tile 0 -> buffer 0
            __nv_bfloat16* kb0 = s16 + (ABUF >> 1);
#pragma unroll
            for (int i = 0; i < 8; i++) {
                int off = prow[i] * ASTR + pcol[i];
                float4 v = *(const float4*)(kg + (size_t)prow[i] * H_ + pcol[i]);
                uint2 hv, lv; bf16_split4(v, hv, lv);
                *(uint2*)(kb0 + (AKH >> 1) + off) = hv;
                *(uint2*)(kb0 + (AKL >> 1) + off) = lv;
                float4 w = *(const float4*)(vg + (size_t)prow[i] * H_ + pcol[i]);
                bf16_split4(w, hv, lv);
                *(uint2*)(kb0 + (AVH >> 1) + off) = hv;
                *(uint2*)(kb0 + (AVL >> 1) + off) = lv;
            }
        }

        float m0 = -1e30f, m1 = -1e30f, l0 = 0.f, l1 = 0.f;
        float o[4][4];
#pragma unroll
        for (int dj = 0; dj < 4; dj++)
#pragma unroll
            for (int q = 0; q < 4; q++) o[dj][q] = 0.f;

        __syncthreads();   // Q + KV0 ready

        for (int kb = 0; kb < ntiles; kb++) {
            const int cur = kb & 1;
            const int key0 = kb * 64;
            const uint32_t bufb = sb + ABUF + cur * ABUFSZ;

            float c[4][4];
            float mx0, mx1, sum0, sum1;

            if (!cons) {
                if (kb + 1 < ntiles) {
                    const int nk0 = key0 + 64;
                    __nv_bfloat16* bufn = s16 + ((ABUF + ((kb + 1) & 1) * ABUFSZ) >> 1);
#pragma unroll
                    for (int i = 0; i < 8; i++) {
                        int off = prow[i] * ASTR + pcol[i];
                        float4 v = *(const float4*)(kg + (size_t)(nk0 + prow[i]) * H_ + pcol[i]);
                        uint2 hv, lv; bf16_split4(v, hv, lv);
                        *(uint2*)(bufn + (AKH >> 1) + off) = hv;
                        *(uint2*)(bufn + (AKL >> 1) + off) = lv;
                        float4 w = *(const float4*)(vg + (size_t)(nk0 + prow[i]) * H_ + pcol[i]);
                        bf16_split4(w, hv, lv);
                        *(uint2*)(bufn + (AVH >> 1) + off) = hv;
                        *(uint2*)(bufn + (AVL >> 1) + off) = lv;
                    }
                }
            } else {
                // ---- S_half = Q @ K_half^T (QhKh + QhKl + QlKh) ----
#pragma unroll
                for (int nj = 0; nj < 4; nj++)
#pragma unroll
                    for (int q = 0; q < 4; q++) c[nj][q] = 0.f;

#pragma unroll
                for (int kk = 0; kk < 4; kk++) {
                    uint32_t qaddr = sb + AQH + (warp_m + a_lrow) * AROWB +
                                     a_koff + kk * 32;
                    uint32_t qh[4], ql[4];
                    LDSM4(qh[0], qh[1], qh[2], qh[3], qaddr);
                    LDSM4(ql[0], ql[1], ql[2], ql[3], qaddr + (AQL - AQH));
#pragma unroll
                    for (int nj = 0; nj < 4; nj++) {
                        uint32_t kaddr = bufb + AKH +
                                         (n_base + nj * 8 + b_lrow) * AROWB +
                                         b_koff + kk * 32;
                        uint32_t kh0, kh1, kl0, kl1;
                        LDSM2(kh0, kh1, kaddr);
                        LDSM2(kl0, kl1, kaddr + (AKL - AKH));
                        mma16816(c[nj], qh[0], qh[1], qh[2], qh[3], kh0, kh1);
                        mma16816(c[nj], qh[0], qh[1], qh[2], qh[3], kl0, kl1);
                        mma16816(c[nj], ql[0], ql[1], ql[2], ql[3], kh0, kh1);
                    }
                }

                // ---- causal mask (diagonal tile only) ----
                if (kb == qb) {
                    const int r0 = q0 + warp_m + qrow;
                    const int nb0 = key0 + n_base + qcol;
#pragma unroll
                    for (int nj = 0; nj < 4; nj++) {
                        int n = nb0 + nj * 8;
                        if (n     > r0)     c[nj][0] = -1e30f;
                        if (n + 1 > r0)     c[nj][1] = -1e30f;
                        if (n     > r0 + 8) c[nj][2] = -1e30f;
                        if (n + 1 > r0 + 8) c[nj][3] = -1e30f;
                    }
                }

                // ---- partial softmax over this key-half ----
                mx0 = -1e30f; mx1 = -1e30f;
#pragma unroll
                for (int nj = 0; nj < 4; nj++) {
                    mx0 = fmaxf(mx0, fmaxf(c[nj][0], c[nj][1]));
                    mx1 = fmaxf(mx1, fmaxf(c[nj][2], c[nj][3]));
                }
                mx0 = fmaxf(mx0, __shfl_xor_sync(0xffffffffu, mx0, 1));
                mx0 = fmaxf(mx0, __shfl_xor_sync(0xffffffffu, mx0, 2));
                mx1 = fmaxf(mx1, __shfl_xor_sync(0xffffffffu, mx1, 1));
                mx1 = fmaxf(mx1, __shfl_xor_sync(0xffffffffu, mx1, 2));

                sum0 = 0.f; sum1 = 0.f;
#pragma unroll
                for (int nj = 0; nj < 4; nj++) {
                    c[nj][0] = __expf(c[nj][0] - mx0); sum0 += c[nj][0];
                    c[nj][1] = __expf(c[nj][1] - mx0); sum0 += c[nj][1];
                    c[nj][2] = __expf(c[nj][2] - mx1); sum1 += c[nj][2];
                    c[nj][3] = __expf(c[nj][3] - mx1); sum1 += c[nj][3];
                }
                sum0 += __shfl_xor_sync(0xffffffffu, sum0, 1);
                sum0 += __shfl_xor_sync(0xffffffffu, sum0, 2);
                sum1 += __shfl_xor_sync(0xffffffffu, sum1, 1);
                sum1 += __shfl_xor_sync(0xffffffffu, sum1, 2);

                if ((lane & 3) == 0) {
                    st[half * 128 + warp_m + qrow]          = mx0;
                    st[half * 128 + warp_m + qrow + 8]      = mx1;
                    st[half * 128 + 64 + warp_m + qrow]     = sum0;
                    st[half * 128 + 64 + warp_m + qrow + 8] = sum1;
                }
            }
            __syncthreads();   // stats visible

            if (cons) {
                // ---- combine halves; online update ----
                float mo0 = st[(half ^ 1) * 128 + warp_m + qrow];
                float mo1 = st[(half ^ 1) * 128 + warp_m + qrow + 8];
                float so0 = st[(half ^ 1) * 128 + 64 + warp_m + qrow];
                float so1 = st[(half ^ 1) * 128 + 64 + warp_m + qrow + 8];
                float mn0 = fmaxf(mx0, mo0), mn1 = fmaxf(mx1, mo1);
                float mw0 = fmaxf(m0, mn0),  mw1 = fmaxf(m1, mn1);
                float corr0 = __expf(m0 - mw0), corr1 = __expf(m1 - mw1);
                float f0 = __expf(mx0 - mw0), f1 = __expf(mx1 - mw1);
                float g0 = __expf(mo0 - mw0), g1 = __expf(mo1 - mw1);
                l0 = l0 * corr0 + sum0 * f0 + so0 * g0;
                l1 = l1 * corr1 + sum1 * f1 + so1 * g1;
                m0 = mw0; m1 = mw1;
#pragma unroll
                for (int dj = 0; dj < 4; dj++) {
                    o[dj][0] *= corr0; o[dj][1] *= corr0;
                    o[dj][2] *= corr1; o[dj][3] *= corr1;
                }

                // ---- scale, pack, stage P in smem ----
#pragma unroll
                for (int nj = 0; nj < 4; nj++) {
                    uint32_t h, l;
                    int col = (n_base + nj * 8 + qcol) * 2;
                    packsplit2(c[nj][0] * f0, c[nj][1] * f0, h, l);
                    int off0 = APH + (warp_m + qrow) * AROWB + col;
                    *(uint32_t*)(smem + off0) = h;
                    *(uint32_t*)(smem + off0 + (APL - APH)) = l;
                    packsplit2(c[nj][2] * f1, c[nj][3] * f1, h, l);
                    int off1 = APH + (warp_m + qrow + 8) * AROWB + col;
                    *(uint32_t*)(smem + off1) = h;
                    *(uint32_t*)(smem + off1 + (APL - APH)) = l;
                }
            }
            __syncthreads();   // P visible

            if (cons) {
                // ---- O_half += P(all keys) @ V(d-half) ----
#pragma unroll
                for (int kk = 0; kk < 4; kk++) {
                    uint32_t paddr = sb + APH + (warp_m + a_lrow) * AROWB +
                                     a_koff + kk * 32;
                    uint32_t ph[4], pl[4];
                    LDSM4(ph[0], ph[1], ph[2], ph[3], paddr);
                    LDSM4(pl[0], pl[1], pl[2], pl[3], paddr + (APL - APH));
                    uint32_t vrow = kk * 16 + ((lane >> 3) & 1) * 8 + (lane & 7);
                    uint32_t vbase = bufb + AVH + vrow * AROWB + n_base * 2;
#pragma unroll
                    for (int dj = 0; dj < 4; dj++) {
                        uint32_t vaddr = vbase + dj * 16;
                        uint32_t vh0, vh1, vl0, vl1;
                        LDSM2T(vh0, vh1, vaddr);
                        LDSM2T(vl0, vl1, vaddr + (AVL - AVH));
                        mma16816(o[dj], ph[0], ph[1], ph[2], ph[3], vh0, vh1);
                        mma16816(o[dj], ph[0], ph[1], ph[2], ph[3], vl0, vl1);
                        mma16816(o[dj], pl[0], pl[1], pl[2], pl[3], vh0, vh1);
                    }
                }
            }
            __syncthreads();   // buffer + P/stat handoff
        }

        // ---- epilogue (consumers) ----
        if (cons) {
            const int r0 = q0 + warp_m + qrow;
            const float inv0 = 1.f / l0, inv1 = 1.f / l1;
#pragma unroll
            for (int dj = 0; dj < 4; dj++) {
                const int d = n_base + dj * 8 + qcol;
                *(float2*)&out[((size_t)b * T_ + r0) * H_ + d] =
                    make_float2(o[dj][0] * inv0, o[dj][1] * inv0);
                *(float2*)&out[((size_t)b * T_ + r0 + 8) * H_ + d] =
                    make_float2(o[dj][2] * inv1, o[dj][3] * inv1);
            }
        }
    }
}

// ---------------------------------------------------------------------------
extern "C" void kernel_launch(void* const* d_in, const int* in_sizes, int n_in,
                              void* d_out, int out_size)
{
    const float* x  = (const float*)d_in[0];
    const float* Wk = (const float*)d_in[1];
    const float* Wq = (const float*)d_in[2];
    const float* Wv = (const float*)d_in[3];
    float* out = (float*)d_out;

    (void)in_sizes; (void)n_in; (void)out_size;

    cudaFuncSetAttribute(proj_kernel,
                         cudaFuncAttributeMaxDynamicSharedMemorySize,
                         PROJ_SMEM);
    cudaFuncSetAttribute(attn_kernel,
                         cudaFuncAttributeMaxDynamicSharedMemorySize,
                         ATTN_SMEM);

    proj_kernel<<<(B_ * T_) / 128, 512, PROJ_SMEM>>>(x, Wk, Wq, Wv);

    dim3 agrid(16, B_);
    attn_kernel<<<agrid, 384, ATTN_SMEM>>>(out);
}

// round 17
// speedup vs baseline: 1.0888x; 1.0888x over previous
#include <cuda_runtime.h>
#include <cuda_bf16.h>
#include <math.h>
#include <stdint.h>

#define B_ 8
#define T_ 2048
#define C_ 1024
#define H_ 64

// Scratch (device globals: allocation-free)
__device__ float g_q[B_ * T_ * H_];     // 8*q (logit scale folded into Wq)
__device__ float g_k[B_ * T_ * H_];
__device__ float g_v[B_ * T_ * H_];

// ===========================================================================
// Warp-level tensor core helpers (sm_80+ features: compile for plain sm_103)
// ===========================================================================
__device__ __forceinline__ uint32_t smem_u32(const void* p) {
    uint32_t a;
    asm("{ .reg .u64 t; cvta.to.shared.u64 t, %1; cvt.u32.u64 %0, t; }"
        : "=r"(a) : "l"(p));
    return a;
}

#define LDSM4(r0, r1, r2, r3, addr) \
    asm volatile("ldmatrix.sync.aligned.m8n8.x4.shared.b16 {%0,%1,%2,%3}, [%4];" \
                 : "=r"(r0), "=r"(r1), "=r"(r2), "=r"(r3) : "r"(addr))
#define LDSM2(r0, r1, addr) \
    asm volatile("ldmatrix.sync.aligned.m8n8.x2.shared.b16 {%0,%1}, [%2];" \
                 : "=r"(r0), "=r"(r1) : "r"(addr))
#define LDSM2T(r0, r1, addr) \
    asm volatile("ldmatrix.sync.aligned.m8n8.x2.trans.shared.b16 {%0,%1}, [%2];" \
                 : "=r"(r0), "=r"(r1) : "r"(addr))

__device__ __forceinline__ void mma16816(float* c,
                                         uint32_t a0, uint32_t a1,
                                         uint32_t a2, uint32_t a3,
                                         uint32_t b0, uint32_t b1) {
    asm volatile(
        "mma.sync.aligned.m16n8k16.row.col.f32.bf16.bf16.f32 "
        "{%0,%1,%2,%3}, {%4,%5,%6,%7}, {%8,%9}, {%0,%1,%2,%3};"
        : "+f"(c[0]), "+f"(c[1]), "+f"(c[2]), "+f"(c[3])
        : "r"(a0), "r"(a1), "r"(a2), "r"(a3), "r"(b0), "r"(b1));
}

// split one float4 into hi/lo bf16x4 (packed as uint2 each)
__device__ __forceinline__ void bf16_split4(float4 v, uint2& hv, uint2& lv) {
    __nv_bfloat16 h0 = __float2bfloat16_rn(v.x);
    __nv_bfloat16 h1 = __float2bfloat16_rn(v.y);
    __nv_bfloat16 h2 = __float2bfloat16_rn(v.z);
    __nv_bfloat16 h3 = __float2bfloat16_rn(v.w);
    __nv_bfloat16 l0 = __float2bfloat16_rn(v.x - __bfloat162float(h0));
    __nv_bfloat16 l1 = __float2bfloat16_rn(v.y - __bfloat162float(h1));
    __nv_bfloat16 l2 = __float2bfloat16_rn(v.z - __bfloat162float(h2));
    __nv_bfloat16 l3 = __float2bfloat16_rn(v.w - __bfloat162float(h3));
    hv.x = (uint32_t)__bfloat16_as_ushort(h0) |
           ((uint32_t)__bfloat16_as_ushort(h1) << 16);
    hv.y = (uint32_t)__bfloat16_as_ushort(h2) |
           ((uint32_t)__bfloat16_as_ushort(h3) << 16);
    lv.x = (uint32_t)__bfloat16_as_ushort(l0) |
           ((uint32_t)__bfloat16_as_ushort(l1) << 16);
    lv.y = (uint32_t)__bfloat16_as_ushort(l2) |
           ((uint32_t)__bfloat16_as_ushort(l3) << 16);
}

// split two fp32 values into packed hi/lo bf16x2
__device__ __forceinline__ void packsplit2(float a, float b,
                                           uint32_t& h, uint32_t& l) {
    __nv_bfloat16 ha = __float2bfloat16_rn(a);
    __nv_bfloat16 hb = __float2bfloat16_rn(b);
    __nv_bfloat16 la = __float2bfloat16_rn(a - __bfloat162float(ha));
    __nv_bfloat16 lb = __float2bfloat16_rn(b - __bfloat162float(hb));
    h = (uint32_t)__bfloat16_as_ushort(ha) |
        ((uint32_t)__bfloat16_as_ushort(hb) << 16);
    l = (uint32_t)__bfloat16_as_ushort(la) |
        ((uint32_t)__bfloat16_as_ushort(lb) << 16);
}

// ---------------------------------------------------------------------------
// Tensor-core projection GEMM (mma.sync bf16 hi/lo split, 3 MMAs per pair):
//   out[m][h] = sum_c x[m][c] * W[h][c],  M=16384, N=192, K=1024.
// Block: 128 M x 192 N, 512 threads = 16 warps (8 x 2), warp tile 16 x 96.
// BK=32, double-buffered smem, 40-bf16 (80 B) row stride.
// ---------------------------------------------------------------------------
#define PSTRB 40
#define BUF_ELE (320 * PSTRB * 2)
#define AH_OFF 0
#define AL_OFF (128 * PSTRB)
#define BH_OFF (256 * PSTRB)
#define BL_OFF (448 * PSTRB)
#define PROJ_SMEM (2 * BUF_ELE * 2)

__global__ __launch_bounds__(512, 1)
void proj_kernel(const float* __restrict__ x,
                 const float* __restrict__ Wk,
                 const float* __restrict__ Wq,
                 const float* __restrict__ Wv)
{
    extern __shared__ __align__(16) char smem[];
    __nv_bfloat16* sb16 = (__nv_bfloat16*)smem;
    const uint32_t sb = smem_u32(smem);

    const int tid = threadIdx.x;
    const int wid = tid >> 5;
    const int lane = tid & 31;
    const int row0 = blockIdx.x * 128;
    const int warp_m = (wid >> 1) * 16;   // 8 m-groups
    const int warp_n = (wid & 1) * 96;    // 2 n-halves

    // A: 1024 float4 -> 2/thread
    int ar[2], ac[2];
#pragma unroll
    for (int i = 0; i < 2; i++) {
        int idx = tid + i * 512;
        ar[i] = idx >> 3;
        ac[i] = (idx & 7) << 2;
    }
    // B: 1536 float4 -> 3/thread
    const float* wp[3];
    float wsc[3];
    int wr[3], wc[3];
#pragma unroll
    for (int i = 0; i < 3; i++) {
        int idx = tid + i * 512;
        int r = idx >> 3;
        wr[i] = r;
        wc[i] = (idx & 7) << 2;
        if (r < 64)       { wp[i] = Wk + (size_t)r * C_;         wsc[i] = 1.f; }
        else if (r < 128) { wp[i] = Wq + (size_t)(r - 64) * C_;  wsc[i] = 8.f; }
        else              { wp[i] = Wv + (size_t)(r - 128) * C_; wsc[i] = 1.f; }
    }

    const uint32_t a_lrow = (uint32_t)(lane & 15);
    const uint32_t a_koff = (uint32_t)((lane >> 4) * 16);
    const uint32_t b_lrow = (uint32_t)(lane & 7);
    const uint32_t b_koff = (uint32_t)(((lane >> 3) & 1) * 16);

    float acc[12][4];
#pragma unroll
    for (int nj = 0; nj < 12; nj++)
#pragma unroll
        for (int q = 0; q < 4; q++) acc[nj][q] = 0.f;

    {
        __nv_bfloat16* base = sb16;
#pragma unroll
        for (int i = 0; i < 2; i++) {
            float4 v = *(const float4*)(x + (size_t)(row0 + ar[i]) * C_ + ac[i]);
            uint2 hv, lv; bf16_split4(v, hv, lv);
            int off = ar[i] * PSTRB + ac[i];
            *(uint2*)(base + AH_OFF + off) = hv;
            *(uint2*)(base + AL_OFF + off) = lv;
        }
#pragma unroll
        for (int i = 0; i < 3; i++) {
            float4 v = *(const float4*)(wp[i] + wc[i]);
            v.x *= wsc[i]; v.y *= wsc[i]; v.z *= wsc[i]; v.w *= wsc[i];
            uint2 hv, lv; bf16_split4(v, hv, lv);
            int off = wr[i] * PSTRB + wc[i];
            *(uint2*)(base + BH_OFF + off) = hv;
            *(uint2*)(base + BL_OFF + off) = lv;
        }
    }
    __syncthreads();

    const int NKT = C_ / 32;
    for (int kt = 0; kt < NKT; kt++) {
        const int cur = kt & 1;
        const bool more = (kt + 1 < NKT);

        float4 rxa[2], rxb[3];
        if (more) {
            const int kc = (kt + 1) * 32;
#pragma unroll
            for (int i = 0; i < 2; i++)
                rxa[i] = *(const float4*)(x + (size_t)(row0 + ar[i]) * C_ + kc + ac[i]);
#pragma unroll
            for (int i = 0; i < 3; i++) {
                float4 v = *(const float4*)(wp[i] + kc + wc[i]);
                v.x *= wsc[i]; v.y *= wsc[i]; v.z *= wsc[i]; v.w *= wsc[i];
                rxb[i] = v;
            }
        }

        const uint32_t bufb = sb + cur * BUF_ELE * 2;
#pragma unroll
        for (int ks = 0; ks < 2; ks++) {
            const uint32_t kb = ks * 32;
            uint32_t ah[4], al[4];
            uint32_t rowa = warp_m + a_lrow;
            uint32_t aaddr = bufb + rowa * (PSTRB * 2) + a_koff + kb;
            LDSM4(ah[0], ah[1], ah[2], ah[3], aaddr);
            LDSM4(al[0], al[1], al[2], al[3], aaddr + AL_OFF * 2);
#pragma unroll
            for (int nj = 0; nj < 12; nj++) {
                uint32_t rowb = warp_n + nj * 8 + b_lrow;
                uint32_t baddr = bufb + BH_OFF * 2 + rowb * (PSTRB * 2) +
                                 b_koff + kb;
                uint32_t bh0, bh1, bl0, bl1;
                LDSM2(bh0, bh1, baddr);
                LDSM2(bl0, bl1, baddr + (BL_OFF - BH_OFF) * 2);
                mma16816(acc[nj], ah[0], ah[1], ah[2], ah[3], bh0, bh1);
                mma16816(acc[nj], ah[0], ah[1], ah[2], ah[3], bl0, bl1);
                mma16816(acc[nj], al[0], al[1], al[2], al[3], bh0, bh1);
            }
        }

        if (more) {
            __nv_bfloat16* base = sb16 + (cur ^ 1) * BUF_ELE;
#pragma unroll
            for (int i = 0; i < 2; i++) {
                uint2 hv, lv; bf16_split4(rxa[i], hv, lv);
                int off = ar[i] * PSTRB + ac[i];
                *(uint2*)(base + AH_OFF + off) = hv;
                *(uint2*)(base + AL_OFF + off) = lv;
            }
#pragma unroll
            for (int i = 0; i < 3; i++) {
                uint2 hv, lv; bf16_split4(rxb[i], hv, lv);
                int off = wr[i] * PSTRB + wc[i];
                *(uint2*)(base + BH_OFF + off) = hv;
                *(uint2*)(base + BL_OFF + off) = lv;
            }
        }
        __syncthreads();
    }

    const int erow = lane >> 2;
    const int ecol = (lane & 3) * 2;
    {
        const int rg = row0 + warp_m + erow;
#pragma unroll
        for (int nj = 0; nj < 12; nj++) {
            const int n = warp_n + nj * 8 + ecol;
            const int s = n >> 6;
            const int h = n & 63;
            float* op = (s == 0) ? g_k : (s == 1) ? g_q : g_v;
            *(float2*)&op[(size_t)rg * H_ + h] =
                make_float2(acc[nj][0], acc[nj][1]);
            *(float2*)&op[(size_t)(rg + 8) * H_ + h] =
                make_float2(acc[nj][2], acc[nj][3]);
        }
    }
}

// ---------------------------------------------------------------------------
// Tensor-core flash attention (mma.sync, bf16 hi/lo split, causal).
// BM=64 q rows, BN=64 keys/tile. 256 threads:
//   warps 0-3 = consumers (m16 each; QK^T + softmax + PV, P in registers)
//   warps 4-7 = producers (LDG fp32 -> split bf16 -> STS, double-buffered KV)
// Paired q-tiles (j, 31-j): 33 equal tiles per block, 128 blocks (16x8).
// Row stride 72 bf16 (144 B): conflict-free ldmatrix.
// ---------------------------------------------------------------------------
// byte offsets into dynamic smem
#define AQH 0
#define AQL 9216
#define ABUF 18432            // two KV buffers follow
#define AKH 0
#define AKL 9216
#define AVH 18432
#define AVL 27648
#define ABUFSZ 36864
#define ASTR 72               // row stride in bf16
#define AROWB 144             // row stride in bytes
#define ATTN_SMEM (ABUF + 2 * ABUFSZ)   // 92160 bytes

__global__ __launch_bounds__(256, 1)
void attn_kernel(float* __restrict__ out)
{
    extern __shared__ __align__(16) char smem[];
    __nv_bfloat16* s16 = (__nv_bfloat16*)smem;
    const uint32_t sb = smem_u32(smem);

    const int tid = threadIdx.x;
    const int wid = tid >> 5;
    const int lane = tid & 31;
    const int b = blockIdx.y;

    const float* qg = g_q + (size_t)b * T_ * H_;
    const float* kg = g_k + (size_t)b * T_ * H_;
    const float* vg = g_v + (size_t)b * T_ * H_;

    // producer load slots (threads 128..255): 64 rows x 64 cols fp32 per tile
    const int pt = tid & 127;
    int prow[8], pcol[8];
#pragma unroll
    for (int i = 0; i < 8; i++) {
        int idx = pt + i * 128;
        prow[i] = idx >> 4;
        pcol[i] = (idx & 15) << 2;
    }

    // consumer constants
    const int warp_m = wid * 16;
    const uint32_t a_lrow = (uint32_t)(lane & 15);
    const uint32_t a_koff = (uint32_t)((lane >> 4) * 16);
    const uint32_t b_lrow = (uint32_t)(lane & 7);
    const uint32_t b_koff = (uint32_t)(((lane >> 3) & 1) * 16);
    const int qrow = lane >> 2;        // local row within m16 (and +8)
    const int qcol = (lane & 3) * 2;   // local col pair base

#pragma unroll 1
    for (int pass = 0; pass < 2; pass++) {
        const int qb = pass ? (31 - (int)blockIdx.x) : (int)blockIdx.x;
        const int q0 = qb * 64;
        const int ntiles = qb + 1;

        __syncthreads();   // previous pass fully consumed before Q/KV0 overwrite

        if (wid >= 4) {
            // Q tile (holds 8*q already)
#pragma unroll
            for (int i = 0; i < 8; i++) {
                float4 v = *(const float4*)(qg + (size_t)(q0 + prow[i]) * H_ + pcol[i]);
                uint2 hv, lv; bf16_split4(v, hv, lv);
                int off = prow[i] * ASTR + pcol[i];
                *(uint2*)(s16 + (AQH >> 1) + off) = hv;
                *(uint2*)(s16 + (AQL >> 1) + off) = lv;
            }
            // KV tile 0 -> buffer 0
            __nv_bfloat16* kb0 = s16 + (ABUF >> 1);
#pragma unroll
            for (int i = 0; i < 8; i++) {
                int off = prow[i] * ASTR + pcol[i];
                float4 v = *(const float4*)(kg + (size_t)prow[i] * H_ + pcol[i]);
                uint2 hv, lv; bf16_split4(v, hv, lv);
                *(uint2*)(kb0 + (AKH >> 1) + off) = hv;
                *(uint2*)(kb0 + (AKL >> 1) + off) = lv;
                float4 w = *(const float4*)(vg + (size_t)prow[i] * H_ + pcol[i]);
                bf16_split4(w, hv, lv);
                *(uint2*)(kb0 + (AVH >> 1) + off) = hv;
                *(uint2*)(kb0 + (AVL >> 1) + off) = lv;
            }
        }

        float m0 = -1e30f, m1 = -1e30f, l0 = 0.f, l1 = 0.f;
        float o[8][4];
#pragma unroll
        for (int dj = 0; dj < 8; dj++)
#pragma unroll
            for (int q = 0; q < 4; q++) o[dj][q] = 0.f;

        __syncthreads();   // Q + KV0 ready

        for (int kb = 0; kb < ntiles; kb++) {
            const int cur = kb & 1;
            const int key0 = kb * 64;

            if (wid >= 4) {
                // produce next KV tile into the other buffer
                if (kb + 1 < ntiles) {
                    const int nk0 = key0 + 64;
                    __nv_bfloat16* bufn = s16 + ((ABUF + ((kb + 1) & 1) * ABUFSZ) >> 1);
#pragma unroll
                    for (int i = 0; i < 8; i++) {
                        int off = prow[i] * ASTR + pcol[i];
                        float4 v = *(const float4*)(kg + (size_t)(nk0 + prow[i]) * H_ + pcol[i]);
                        uint2 hv, lv; bf16_split4(v, hv, lv);
                        *(uint2*)(bufn + (AKH >> 1) + off) = hv;
                        *(uint2*)(bufn + (AKL >> 1) + off) = lv;
                        float4 w = *(const float4*)(vg + (size_t)(nk0 + prow[i]) * H_ + pcol[i]);
                        bf16_split4(w, hv, lv);
                        *(uint2*)(bufn + (AVH >> 1) + off) = hv;
                        *(uint2*)(bufn + (AVL >> 1) + off) = lv;
                    }
                }
            } else {
                const uint32_t bufb = sb + ABUF + cur * ABUFSZ;

                // ---- S = Q @ K^T (hi/lo split: QhKh + QhKl + QlKh) ----
                float c[8][4];
#pragma unroll
                for (int nj = 0; nj < 8; nj++)
#pragma unroll
                    for (int q = 0; q < 4; q++) c[nj][q] = 0.f;

#pragma unroll
                for (int kk = 0; kk < 4; kk++) {
                    uint32_t qaddr = sb + AQH + (warp_m + a_lrow) * AROWB +
                                     a_koff + kk * 32;
                    uint32_t qh[4], ql[4];
                    LDSM4(qh[0], qh[1], qh[2], qh[3], qaddr);
                    LDSM4(ql[0], ql[1], ql[2], ql[3], qaddr + (AQL - AQH));
#pragma unroll
                    for (int nj = 0; nj < 8; nj++) {
                        uint32_t kaddr = bufb + AKH + (nj * 8 + b_lrow) * AROWB +
                                         b_koff + kk * 32;
                        uint32_t kh0, kh1, kl0, kl1;
                        LDSM2(kh0, kh1, kaddr);
                        LDSM2(kl0, kl1, kaddr + (AKL - AKH));
                        mma16816(c[nj], qh[0], qh[1], qh[2], qh[3], kh0, kh1);
                        mma16816(c[nj], qh[0], qh[1], qh[2], qh[3], kl0, kl1);
                        mma16816(c[nj], ql[0], ql[1], ql[2], ql[3], kh0, kh1);
                    }
                }

                // ---- causal mask (diagonal tile only) ----
                if (kb == qb) {
                    const int r0 = q0 + warp_m + qrow;
                    const int n0 = key0 + qcol;
#pragma unroll
                    for (int nj = 0; nj < 8; nj++) {
                        int n = n0 + nj * 8;
                        if (n     > r0)     c[nj][0] = -1e30f;
                        if (n + 1 > r0)     c[nj][1] = -1e30f;
                        if (n     > r0 + 8) c[nj][2] = -1e30f;
                        if (n + 1 > r0 + 8) c[nj][3] = -1e30f;
                    }
                }

                // ---- online softmax (rows r and r+8; quad reductions) ----
                float mx0 = -1e30f, mx1 = -1e30f;
#pragma unroll
                for (int nj = 0; nj < 8; nj++) {
                    mx0 = fmaxf(mx0, fmaxf(c[nj][0], c[nj][1]));
                    mx1 = fmaxf(mx1, fmaxf(c[nj][2], c[nj][3]));
                }
                mx0 = fmaxf(mx0, __shfl_xor_sync(0xffffffffu, mx0, 1));
                mx0 = fmaxf(mx0, __shfl_xor_sync(0xffffffffu, mx0, 2));
                mx1 = fmaxf(mx1, __shfl_xor_sync(0xffffffffu, mx1, 1));
                mx1 = fmaxf(mx1, __shfl_xor_sync(0xffffffffu, mx1, 2));
                float mn0 = fmaxf(m0, mx0), mn1 = fmaxf(m1, mx1);
                float corr0 = __expf(m0 - mn0), corr1 = __expf(m1 - mn1);
                m0 = mn0; m1 = mn1;

                float sum0 = 0.f, sum1 = 0.f;
#pragma unroll
                for (int nj = 0; nj < 8; nj++) {
                    c[nj][0] = __expf(c[nj][0] - mn0); sum0 += c[nj][0];
                    c[nj][1] = __expf(c[nj][1] - mn0); sum0 += c[nj][1];
                    c[nj][2] = __expf(c[nj][2] - mn1); sum1 += c[nj][2];
                    c[nj][3] = __expf(c[nj][3] - mn1); sum1 += c[nj][3];
                }
                sum0 += __shfl_xor_sync(0xffffffffu, sum0, 1);
                sum0 += __shfl_xor_sync(0xffffffffu, sum0, 2);
                sum1 += __shfl_xor_sync(0xffffffffu, sum1, 1);
                sum1 += __shfl_xor_sync(0xffffffffu, sum1, 2);
                l0 = l0 * corr0 + sum0;
                l1 = l1 * corr1 + sum1;
#pragma unroll
                for (int dj = 0; dj < 8; dj++) {
                    o[dj][0] *= corr0; o[dj][1] *= corr0;
                    o[dj][2] *= corr1; o[dj][3] *= corr1;
                }

                // ---- pack P (C-frag -> A-frag, hi/lo) ----
                uint32_t ph[4][4], pl[4][4];
#pragma unroll
                for (int kk = 0; kk < 4; kk++) {
                    packsplit2(c[2 * kk][0],     c[2 * kk][1],     ph[kk][0], pl[kk][0]);
                    packsplit2(c[2 * kk][2],     c[2 * kk][3],     ph[kk][1], pl[kk][1]);
                    packsplit2(c[2 * kk + 1][0], c[2 * kk + 1][1], ph[kk][2], pl[kk][2]);
                    packsplit2(c[2 * kk + 1][2], c[2 * kk + 1][3], ph[kk][3], pl[kk][3]);
                }

                // ---- O += P @ V (V via ldmatrix.trans; PhVh + PhVl + PlVh) ----
#pragma unroll
                for (int kk = 0; kk < 4; kk++) {
                    uint32_t vrow = kk * 16 + ((lane >> 3) & 1) * 8 + (lane & 7);
                    uint32_t vbase = bufb + AVH + vrow * AROWB;
#pragma unroll
                    for (int dj = 0; dj < 8; dj++) {
                        uint32_t vaddr = vbase + dj * 16;
                        uint32_t vh0, vh1, vl0, vl1;
                        LDSM2T(vh0, vh1, vaddr);
                        LDSM2T(vl0, vl1, vaddr + (AVL - AVH));
                        mma16816(o[dj], ph[kk][0], ph[kk][1], ph[kk][2],
                                 ph[kk][3], vh0, vh1);
                        mma16816(o[dj], ph[kk][0], ph[kk][1], ph[kk][2],
                                 ph[kk][3], vl0, vl1);
                        mma16816(o[dj], pl[kk][0], pl[kk][1], pl[kk][2],
                                 pl[kk][3], vh0, vh1);
                    }
                }
            }
            __syncthreads();   // buffer handoff
        }

        // ---- epilogue (consumers) ----
        if (wid < 4) {
            const int r0 = q0 + warp_m + qrow;
            const float inv0 = 1.f / l0, inv1 = 1.f / l1;
#pragma unroll
            for (int dj = 0; dj < 8; dj++) {
                const int d = dj * 8 + qcol;
                *(float2*)&out[((size_t)b * T_ + r0) * H_ + d] =
                    make_float2(o[dj][0] * inv0, o[dj][1] * inv0);
                *(float2*)&out[((size_t)b * T_ + r0 + 8) * H_ + d] =
                    make_float2(o[dj][2] * inv1, o[dj][3] * inv1);
            }
        }
    }
}

// ---------------------------------------------------------------------------
extern "C" void kernel_launch(void* const* d_in, const int* in_sizes, int n_in,
                              void* d_out, int out_size)
{
    const float* x  = (const float*)d_in[0];
    const float* Wk = (const float*)d_in[1];
    const float* Wq = (const float*)d_in[2];
    const float* Wv = (const float*)d_in[3];
    float* out = (float*)d_out;

    (void)in_sizes; (void)n_in; (void)out_size;

    cudaFuncSetAttribute(proj_kernel,
                         cudaFuncAttributeMaxDynamicSharedMemorySize,
                         PROJ_SMEM);
    cudaFuncSetAttribute(attn_kernel,
                         cudaFuncAttributeMaxDynamicSharedMemorySize,
                         ATTN_SMEM);

    proj_kernel<<<(B_ * T_) / 128, 512, PROJ_SMEM>>>(x, Wk, Wq, Wv);

    dim3 agrid(16, B_);
    attn_kernel<<<agrid, 256, ATTN_SMEM>>>(out);
}